// round 13
// baseline (speedup 1.0000x reference)
#include <cuda_runtime.h>
#include <cstdint>

#define BB 16
#define NN 2000
#define DD 128
#define OO 64
#define NL 3
#define NPAD 2048
#define BN (BB*NN)
#define NCH 125
#define CH 16
#define GT 25
#define NP1 (NN+1)
#define HSS 36

__device__ float g_h[BN*DD];
__device__ float g_Wh[BN*DD];
__device__ float g_e1[2][BN];
__device__ float g_e2[BN];
__device__ float g_e2max[BB];
__device__ int   g_perm[BB*NPAD];
__device__ int   g_k[BN];
__device__ float g_u1[BB*NN];
__device__ float g_u2[BB*NN];
__device__ unsigned long long g_ck[BB*2048];
__device__ float g_P2l[BB*NP1*DD];
__device__ float g_P1l[BB*NP1*DD];
__device__ float g_P2ls[BB*NP1];
__device__ float g_P1ls[BB*NP1];
__device__ float g_chF[BB*NCH*DD];
__device__ float g_chB[BB*NCH*DD];
__device__ float g_chF2[BB*NCH*DD];
__device__ float g_chB2[BB*NCH*DD];
__device__ float g_chFs[BB*NCH];
__device__ float g_chBs[BB*NCH];
__device__ float g_chFs2[BB*NCH];
__device__ float g_chBs2[BB*NCH];
__device__ float g_TB[BB*DD];
__device__ float g_TBs[BB];

// ---------- f32x2 packed helpers ----------
__device__ __forceinline__ unsigned long long pk2(float lo, float hi) {
    unsigned long long r;
    asm("mov.b64 %0, {%1, %2};" : "=l"(r)
        : "r"(__float_as_uint(lo)), "r"(__float_as_uint(hi)));
    return r;
}
__device__ __forceinline__ void upk2(unsigned long long v, float& lo, float& hi) {
    unsigned int a, b;
    asm("mov.b64 {%0, %1}, %2;" : "=r"(a), "=r"(b) : "l"(v));
    lo = __uint_as_float(a); hi = __uint_as_float(b);
}
__device__ __forceinline__ unsigned long long fma2(unsigned long long a,
                                                   unsigned long long b,
                                                   unsigned long long c) {
    unsigned long long d;
    asm("fma.rn.f32x2 %0, %1, %2, %3;" : "=l"(d) : "l"(a), "l"(b), "l"(c));
    return d;
}
__device__ __forceinline__ unsigned int xf(float f) {
    unsigned int u = __float_as_uint(f);
    return (u & 0x80000000u) ? ~u : (u | 0x80000000u);
}
__device__ __forceinline__ float ixf(unsigned int u) {
    unsigned int b = (u & 0x80000000u) ? (u & 0x7FFFFFFFu) : ~u;
    return __uint_as_float(b);
}

__device__ __forceinline__ void gemm32(const float* __restrict__ M, const float* hs,
                                       int t, int ldm, unsigned long long* acc) {
#pragma unroll 2
    for (int k = 0; k < DD; k++) {
        float wv = M[k*ldm + t];
        unsigned long long w2 = pk2(wv, wv);
        const float4* hp = (const float4*)(hs + k*HSS);
#pragma unroll
        for (int q = 0; q < 8; q++) {
            float4 h4 = hp[q];
            acc[2*q]   = fma2(pk2(h4.x, h4.y), w2, acc[2*q]);
            acc[2*q+1] = fma2(pk2(h4.z, h4.w), w2, acc[2*q+1]);
        }
    }
}

// ---------- combine: per-node scalars from tables ----------
__device__ __forceinline__ void combine_prelude(int node, const float* __restrict__ e1src,
                                                int* s_ro_ch, int* s_ro_k, int* s_tb,
                                                float* s_a, float* s_be, float* s_inv,
                                                int slot) {
    int b = node / NN;
    int k = g_k[node];
    int c = k >> 4; if (c > NCH - 1) c = NCH - 1;
    float e1v = e1src[node];
    float tt = e1v + g_e2max[b];
    float m = fmaxf(tt, 0.2f * tt);
    float alpha = __expf(tt - m);
    float beta  = __expf(0.2f * tt - m);
    float P2s = g_chFs2[b*NCH + c] + g_P2ls[b*NP1 + k];
    float S1s = g_TBs[b] - (g_chBs2[b*NCH + c] + g_P1ls[b*NP1 + k]);
    float Z = alpha * S1s + beta * P2s;
    s_ro_ch[slot] = (b*NCH + c)*DD;
    s_ro_k[slot]  = (b*NP1 + k)*DD;
    s_tb[slot]    = b*DD;
    s_a[slot] = alpha; s_be[slot] = beta; s_inv[slot] = 1.0f / Z;
}
__device__ __forceinline__ float combine_val(int ro_ch, int ro_k, int tb,
                                             float a, float be, float inv, int d) {
    float P2v = g_chF2[ro_ch + d] + g_P2l[ro_k + d];
    float S1v = g_TB[tb + d] - (g_chB2[ro_ch + d] + g_P1l[ro_k + d]);
    float num = a * S1v + be * P2v;
    return fmaxf(num * inv, 0.f);
}

// ---------------- encoder ----------------
__global__ void enc_kernel(const float* __restrict__ coords, const float* __restrict__ w0,
                           const float* __restrict__ b0, const float* __restrict__ w1,
                           const float* __restrict__ b1) {
    __shared__ float hs[DD*HSS];
    __shared__ float cxy[64];
    int t = threadIdx.x;
    int base = blockIdx.x * 32;
    if (t < 64) cxy[t] = coords[(size_t)base*2 + t];
    __syncthreads();
    float w00 = w0[t], w01 = w0[DD + t], bb = b0[t];
#pragma unroll
    for (int i = 0; i < 32; i++)
        hs[t*HSS + i] = fmaxf(fmaf(cxy[2*i], w00, fmaf(cxy[2*i+1], w01, bb)), 0.f);
    __syncthreads();
    unsigned long long acc[16];
    float bv = b1[t];
    unsigned long long b2 = pk2(bv, bv);
#pragma unroll
    for (int q = 0; q < 16; q++) acc[q] = b2;
    gemm32(w1, hs, t, DD, acc);
#pragma unroll
    for (int q = 0; q < 16; q++) {
        float lo, hi; upk2(acc[q], lo, hi);
        int i = 2*q;
        g_h[(size_t)(base + i)*DD + t] = lo;
        g_h[(size_t)(base + i + 1)*DD + t] = hi;
    }
}

// ---------------- Wh = h @ W + fused e1/e2 (+ optional fused combine) ----------------
template<bool FUSED>
__global__ void whe_kernel(const float* __restrict__ W, const float* __restrict__ a1,
                           const float* __restrict__ a2, int p) {
    __shared__ float hs[DD*HSS];
    __shared__ float red[2][4][32];
    __shared__ int s_ro_ch[32], s_ro_k[32], s_tb[32];
    __shared__ float s_a[32], s_be[32], s_inv[32];
    int t = threadIdx.x;              // 128
    int base = blockIdx.x * 32;
    if (FUSED) {
        if (t < 32)
            combine_prelude(base + t, g_e1[1 - p], s_ro_ch, s_ro_k, s_tb,
                            s_a, s_be, s_inv, t);
        __syncthreads();
#pragma unroll 4
        for (int i = 0; i < 32; i++)
            hs[t*HSS + i] = combine_val(s_ro_ch[i], s_ro_k[i], s_tb[i],
                                        s_a[i], s_be[i], s_inv[i], t);
    } else {
#pragma unroll
        for (int i = 0; i < 32; i++) hs[t*HSS + i] = g_h[(size_t)(base + i)*DD + t];
    }
    __syncthreads();
    unsigned long long acc[16];
#pragma unroll
    for (int q = 0; q < 16; q++) acc[q] = 0ull;
    gemm32(W, hs, t, DD, acc);
    float vals[32];
#pragma unroll
    for (int q = 0; q < 16; q++) upk2(acc[q], vals[2*q], vals[2*q+1]);
#pragma unroll
    for (int i = 0; i < 32; i++) g_Wh[(size_t)(base + i)*DD + t] = vals[i];
    float a1t = a1[t], a2t = a2[t];
    int lane = t & 31, w2i = t >> 5;
#pragma unroll
    for (int i = 0; i < 32; i++) {
        float s1 = vals[i] * a1t, s2 = vals[i] * a2t;
#pragma unroll
        for (int off = 16; off; off >>= 1) {
            s1 += __shfl_xor_sync(0xffffffffu, s1, off);
            s2 += __shfl_xor_sync(0xffffffffu, s2, off);
        }
        if (lane == 0) { red[0][w2i][i] = s1; red[1][w2i][i] = s2; }
    }
    __syncthreads();
    if (t < 64) {
        int which = t >> 5, i = t & 31;
        float s = red[which][0][i] + red[which][1][i] + red[which][2][i] + red[which][3][i];
        if (which == 0) g_e1[p][base + i] = s; else g_e2[base + i] = s;
    }
}

// ---------------- csort: warp-sorted 128-elem chunks of packed keys ----------------
__device__ __forceinline__ void ce64(unsigned long long& a, unsigned long long& b,
                                     bool up) {
    if (up ? (a > b) : (a < b)) { unsigned long long t = a; a = b; b = t; }
}

__global__ void __launch_bounds__(512) csort_kernel() {
    int b = blockIdx.x;
    int w = threadIdx.x >> 5, lane = threadIdx.x & 31;
    unsigned long long v[4];
#pragma unroll
    for (int q = 0; q < 4; q++) {
        int e = lane + 32*q;
        int idx = w*125 + e;
        v[q] = (e < 125)
             ? (((unsigned long long)xf(g_e2[b*NN + idx]) << 11) | (unsigned int)idx)
             : 0xFFFFFFFFFFFFFFFFull;
    }
#pragma unroll
    for (int k = 2; k <= 128; k <<= 1) {
        // in-thread exchanges for j = 64, 32 (when j <= k/2)
#pragma unroll
        for (int j = 64; j >= 32; j >>= 1) {
            if (j <= (k >> 1)) {
                int qb = j >> 5;
#pragma unroll
                for (int qa = 0; qa < 4; qa++) {
                    if ((qa & qb) == 0) {
                        bool up = (((lane + 32*qa) & k) == 0);
                        ce64(v[qa], v[qa | qb], up);
                    }
                }
            }
        }
        int j0 = ((k >> 1) < 16) ? (k >> 1) : 16;
        for (int j = j0; j >= 1; j >>= 1) {
#pragma unroll
            for (int q = 0; q < 4; q++) {
                unsigned long long pv = __shfl_xor_sync(0xffffffffu, v[q], j);
                bool up = (((lane + 32*q) & k) == 0);
                bool lower = ((lane & j) == 0);
                bool asc = (lower == up);
                if (asc ? (pv < v[q]) : (pv > v[q])) v[q] = pv;
            }
        }
    }
#pragma unroll
    for (int q = 0; q < 4; q++)
        g_ck[b*2048 + w*128 + lane + 32*q] = v[q];
}

// ---------------- rank: per-node rank & breakpoint via 16 binary searches ----------------
__global__ void __launch_bounds__(128) rank_kernel(int p) {
    __shared__ unsigned long long sk[2048];
    int blk = blockIdx.x;
    int b = blk >> 4, sub = blk & 15;
    int tid = threadIdx.x;
    for (int i = tid; i < 2048; i += 128) sk[i] = g_ck[b*2048 + i];
    __syncthreads();
    // e2max = max over chunk maxima (position 124 = largest real key per chunk)
    unsigned int um = 0;
#pragma unroll
    for (int c = 0; c < 16; c++) {
        unsigned int ux = (unsigned int)(sk[c*128 + 124] >> 11);
        um = um > ux ? um : ux;
    }
    float e2m = ixf(um);
    if (sub == 0 && tid == 0) g_e2max[b] = e2m;
    if (tid < 125) {
        int j = sub*125 + tid;
        float e2j = g_e2[b*NN + j];
        unsigned long long keyj = ((unsigned long long)xf(e2j) << 11) | (unsigned int)j;
        unsigned long long keyk = ((unsigned long long)xf(-g_e1[p][b*NN + j]) << 11);
        int rank = 0, kcnt = 0;
#pragma unroll
        for (int c = 0; c < 16; c++) {
            int cb = c*128;
            int lo1 = 0, lo2 = 0;
#pragma unroll
            for (int half = 64; half >= 1; half >>= 1) {
                if (sk[cb + lo1 + half - 1] < keyj) lo1 += half;
                if (sk[cb + lo2 + half - 1] < keyk) lo2 += half;
            }
            lo1 += (sk[cb + lo1] < keyj);
            lo2 += (sk[cb + lo2] < keyk);
            rank += lo1; kcnt += lo2;
        }
        g_perm[b*NPAD + rank] = j;
        float ev = e2j - e2m;
        g_u1[b*NN + rank] = __expf(ev);
        g_u2[b*NN + rank] = __expf(0.2f * ev);
        g_k[b*NN + j] = kcnt;
    }
}

// ---------------- scanAB: gather once; emit local prefix tables + chunk totals ----------------
__global__ void scanAB_kernel() {
    __shared__ float su1[CH], su2[CH];
    __shared__ int sperm[CH];
    int b = blockIdx.x / NCH, c = blockIdx.x % NCH;
    int d = threadIdx.x;
    int k0 = c * CH;
    if (d < CH) {
        su1[d] = g_u1[b*NN + k0 + d];
        su2[d] = g_u2[b*NN + k0 + d];
        sperm[d] = g_perm[b*NPAD + k0 + d];
    }
    __syncthreads();
    float w[CH];
#pragma unroll
    for (int k = 0; k < CH; k++) w[k] = g_Wh[((size_t)b*NN + sperm[k])*DD + d];
    size_t rowbase = ((size_t)b*NP1 + k0)*DD + d;
    float f = 0.f, bk = 0.f;
#pragma unroll
    for (int k = 0; k < CH; k++) {
        g_P2l[rowbase + (size_t)k*DD] = f;
        g_P1l[rowbase + (size_t)k*DD] = bk;
        f  = fmaf(su2[k], w[k], f);
        bk = fmaf(su1[k], w[k], bk);
    }
    if (c == NCH - 1) {
        g_P2l[rowbase + (size_t)CH*DD] = f;
        g_P1l[rowbase + (size_t)CH*DD] = bk;
    }
    g_chF[(b*NCH + c)*DD + d] = f;
    g_chB[(b*NCH + c)*DD + d] = bk;
    if (d == 0) {
        float s = 0.f;
#pragma unroll
        for (int k = 0; k < CH; k++) { g_P2ls[b*NP1 + k0 + k] = s; s += su2[k]; }
        if (c == NCH - 1) g_P2ls[b*NP1 + NN] = s;
        g_chFs[b*NCH + c] = s;
    }
    if (d == 1) {
        float s = 0.f;
#pragma unroll
        for (int k = 0; k < CH; k++) { g_P1ls[b*NP1 + k0 + k] = s; s += su1[k]; }
        if (c == NCH - 1) g_P1ls[b*NP1 + NN] = s;
        g_chBs[b*NCH + c] = s;
    }
}

// ---------------- scanC: F and B chains in separate blocks (grid = 2*BB) ----------------
__global__ void scanC_kernel() {
    int b = blockIdx.x >> 1;
    bool isF = (blockIdx.x & 1) == 0;
    int d = threadIdx.x;
    const float* src = isF ? g_chF : g_chB;
    float* dst = isF ? g_chF2 : g_chB2;
    float s = 0.f;
    float v[GT];
    for (int tile = 0; tile < 5; tile++) {
        int c0 = tile*GT;
#pragma unroll
        for (int r = 0; r < GT; r++) v[r] = src[(b*NCH + c0 + r)*DD + d];
#pragma unroll
        for (int r = 0; r < GT; r++) { float x = v[r]; v[r] = s; s += x; }
#pragma unroll
        for (int r = 0; r < GT; r++) dst[(b*NCH + c0 + r)*DD + d] = v[r];
    }
    if (!isF) g_TB[b*DD + d] = s;
    if (d == 0) {
        const float* ssrc = isF ? g_chFs : g_chBs;
        float* sdst = isF ? g_chFs2 : g_chBs2;
        float sc = 0.f;
#pragma unroll 5
        for (int c = 0; c < NCH; c++) {
            float x = ssrc[b*NCH + c];
            sdst[b*NCH + c] = sc;
            sc += x;
        }
        if (!isF) g_TBs[b] = sc;
    }
}

// ---------------- proj (fused combine) ----------------
__global__ void proj_kernel(const float* __restrict__ pw, const float* __restrict__ pb,
                            float* __restrict__ out, int p) {
    __shared__ float hs[DD*HSS];
    __shared__ int s_ro_ch[32], s_ro_k[32], s_tb[32];
    __shared__ float s_a[32], s_be[32], s_inv[32];
    int t = threadIdx.x;              // 64
    int base = blockIdx.x * 32;
    if (t < 32)
        combine_prelude(base + t, g_e1[p], s_ro_ch, s_ro_k, s_tb, s_a, s_be, s_inv, t);
    __syncthreads();
#pragma unroll 2
    for (int i = 0; i < 32; i++) {
        hs[t*HSS + i]        = combine_val(s_ro_ch[i], s_ro_k[i], s_tb[i],
                                           s_a[i], s_be[i], s_inv[i], t);
        hs[(t + 64)*HSS + i] = combine_val(s_ro_ch[i], s_ro_k[i], s_tb[i],
                                           s_a[i], s_be[i], s_inv[i], t + 64);
    }
    __syncthreads();
    unsigned long long acc[16];
    float bv = pb[t];
    unsigned long long b2 = pk2(bv, bv);
#pragma unroll
    for (int q = 0; q < 16; q++) acc[q] = b2;
    gemm32(pw, hs, t, OO, acc);
#pragma unroll
    for (int q = 0; q < 16; q++) {
        float lo, hi; upk2(acc[q], lo, hi);
        int i = 2*q;
        out[(size_t)(base + i)*OO + t] = lo;
        out[(size_t)(base + i + 1)*OO + t] = hi;
    }
}

extern "C" void kernel_launch(void* const* d_in, const int* in_sizes, int n_in,
                              void* d_out, int out_size) {
    const float* coords = (const float*)d_in[0];
    const float* enc_w0 = (const float*)d_in[1];
    const float* enc_b0 = (const float*)d_in[2];
    const float* enc_w1 = (const float*)d_in[3];
    const float* enc_b1 = (const float*)d_in[4];
    const float* gat_W  = (const float*)d_in[5];
    const float* gat_a1 = (const float*)d_in[6];
    const float* gat_a2 = (const float*)d_in[7];
    const float* proj_w = (const float*)d_in[8];
    const float* proj_b = (const float*)d_in[9];
    float* out = (float*)d_out;

    enc_kernel<<<BN/32, 128>>>(coords, enc_w0, enc_b0, enc_w1, enc_b1);
    for (int l = 0; l < NL; l++) {
        int p = l & 1;
        if (l == 0)
            whe_kernel<false><<<BN/32, 128>>>(gat_W, gat_a1, gat_a2, p);
        else
            whe_kernel<true><<<BN/32, 128>>>(gat_W + (size_t)l*DD*DD,
                                             gat_a1 + l*DD, gat_a2 + l*DD, p);
        csort_kernel<<<BB, 512>>>();
        rank_kernel<<<BB*16, 128>>>(p);
        scanAB_kernel<<<BB*NCH, 128>>>();
        scanC_kernel<<<2*BB, 128>>>();
    }
    proj_kernel<<<BN/32, 64>>>(proj_w, proj_b, out, (NL - 1) & 1);
}

// round 14
// speedup vs baseline: 1.0131x; 1.0131x over previous
#include <cuda_runtime.h>
#include <cstdint>

#define BB 16
#define NN 2000
#define DD 128
#define OO 64
#define NL 3
#define NPAD 2048
#define BN (BB*NN)
#define NCH 125
#define CH 16
#define GT 25
#define NP1 (NN+1)
#define HSS 36
#define CKS 129   // smem chunk stride (banks: 129*8/4 = 258 ≡ 2 mod 32)

__device__ float g_h[BN*DD];
__device__ float g_Wh[BN*DD];
__device__ float g_e1[2][BN];
__device__ float g_e2[BN];
__device__ float g_e2max[BB];
__device__ int   g_perm[BB*NPAD];
__device__ int   g_k[BN];
__device__ float g_u1[BB*NN];
__device__ float g_u2[BB*NN];
__device__ unsigned long long g_ck[BB*2048];
__device__ float g_P2l[BB*NP1*DD];
__device__ float g_P1l[BB*NP1*DD];
__device__ float g_P2ls[BB*NP1];
__device__ float g_P1ls[BB*NP1];
__device__ float g_chF[BB*NCH*DD];
__device__ float g_chB[BB*NCH*DD];
__device__ float g_chF2[BB*NCH*DD];
__device__ float g_chB2[BB*NCH*DD];
__device__ float g_chFs[BB*NCH];
__device__ float g_chBs[BB*NCH];
__device__ float g_chFs2[BB*NCH];
__device__ float g_chBs2[BB*NCH];
__device__ float g_TB[BB*DD];
__device__ float g_TBs[BB];

// ---------- f32x2 packed helpers ----------
__device__ __forceinline__ unsigned long long pk2(float lo, float hi) {
    unsigned long long r;
    asm("mov.b64 %0, {%1, %2};" : "=l"(r)
        : "r"(__float_as_uint(lo)), "r"(__float_as_uint(hi)));
    return r;
}
__device__ __forceinline__ void upk2(unsigned long long v, float& lo, float& hi) {
    unsigned int a, b;
    asm("mov.b64 {%0, %1}, %2;" : "=r"(a), "=r"(b) : "l"(v));
    lo = __uint_as_float(a); hi = __uint_as_float(b);
}
__device__ __forceinline__ unsigned long long fma2(unsigned long long a,
                                                   unsigned long long b,
                                                   unsigned long long c) {
    unsigned long long d;
    asm("fma.rn.f32x2 %0, %1, %2, %3;" : "=l"(d) : "l"(a), "l"(b), "l"(c));
    return d;
}
__device__ __forceinline__ unsigned int xf(float f) {
    unsigned int u = __float_as_uint(f);
    return (u & 0x80000000u) ? ~u : (u | 0x80000000u);
}
__device__ __forceinline__ float ixf(unsigned int u) {
    unsigned int b = (u & 0x80000000u) ? (u & 0x7FFFFFFFu) : ~u;
    return __uint_as_float(b);
}

__device__ __forceinline__ void gemm32(const float* __restrict__ M, const float* hs,
                                       int t, int ldm, unsigned long long* acc) {
#pragma unroll 2
    for (int k = 0; k < DD; k++) {
        float wv = M[k*ldm + t];
        unsigned long long w2 = pk2(wv, wv);
        const float4* hp = (const float4*)(hs + k*HSS);
#pragma unroll
        for (int q = 0; q < 8; q++) {
            float4 h4 = hp[q];
            acc[2*q]   = fma2(pk2(h4.x, h4.y), w2, acc[2*q]);
            acc[2*q+1] = fma2(pk2(h4.z, h4.w), w2, acc[2*q+1]);
        }
    }
}

// ---------- combine: per-node scalars from tables ----------
__device__ __forceinline__ void combine_prelude(int node, const float* __restrict__ e1src,
                                                int* s_ro_ch, int* s_ro_k, int* s_tb,
                                                float* s_a, float* s_be, float* s_inv,
                                                int slot) {
    int b = node / NN;
    int k = g_k[node];
    int c = k >> 4; if (c > NCH - 1) c = NCH - 1;
    float e1v = e1src[node];
    float tt = e1v + g_e2max[b];
    float m = fmaxf(tt, 0.2f * tt);
    float alpha = __expf(tt - m);
    float beta  = __expf(0.2f * tt - m);
    float P2s = g_chFs2[b*NCH + c] + g_P2ls[b*NP1 + k];
    float S1s = g_TBs[b] - (g_chBs2[b*NCH + c] + g_P1ls[b*NP1 + k]);
    float Z = alpha * S1s + beta * P2s;
    s_ro_ch[slot] = (b*NCH + c)*DD;
    s_ro_k[slot]  = (b*NP1 + k)*DD;
    s_tb[slot]    = b*DD;
    s_a[slot] = alpha; s_be[slot] = beta; s_inv[slot] = 1.0f / Z;
}
__device__ __forceinline__ float combine_val(int ro_ch, int ro_k, int tb,
                                             float a, float be, float inv, int d) {
    float P2v = g_chF2[ro_ch + d] + g_P2l[ro_k + d];
    float S1v = g_TB[tb + d] - (g_chB2[ro_ch + d] + g_P1l[ro_k + d]);
    float num = a * S1v + be * P2v;
    return fmaxf(num * inv, 0.f);
}

// ---------------- encoder ----------------
__global__ void enc_kernel(const float* __restrict__ coords, const float* __restrict__ w0,
                           const float* __restrict__ b0, const float* __restrict__ w1,
                           const float* __restrict__ b1) {
    __shared__ float hs[DD*HSS];
    __shared__ float cxy[64];
    int t = threadIdx.x;
    int base = blockIdx.x * 32;
    if (t < 64) cxy[t] = coords[(size_t)base*2 + t];
    __syncthreads();
    float w00 = w0[t], w01 = w0[DD + t], bb = b0[t];
#pragma unroll
    for (int i = 0; i < 32; i++)
        hs[t*HSS + i] = fmaxf(fmaf(cxy[2*i], w00, fmaf(cxy[2*i+1], w01, bb)), 0.f);
    __syncthreads();
    unsigned long long acc[16];
    float bv = b1[t];
    unsigned long long b2 = pk2(bv, bv);
#pragma unroll
    for (int q = 0; q < 16; q++) acc[q] = b2;
    gemm32(w1, hs, t, DD, acc);
#pragma unroll
    for (int q = 0; q < 16; q++) {
        float lo, hi; upk2(acc[q], lo, hi);
        int i = 2*q;
        g_h[(size_t)(base + i)*DD + t] = lo;
        g_h[(size_t)(base + i + 1)*DD + t] = hi;
    }
}

// ---------------- Wh = h @ W + fused e1/e2 (+ optional fused combine) ----------------
template<bool FUSED>
__global__ void whe_kernel(const float* __restrict__ W, const float* __restrict__ a1,
                           const float* __restrict__ a2, int p) {
    __shared__ float hs[DD*HSS];
    __shared__ float red[2][4][32];
    __shared__ int s_ro_ch[32], s_ro_k[32], s_tb[32];
    __shared__ float s_a[32], s_be[32], s_inv[32];
    int t = threadIdx.x;              // 128
    int base = blockIdx.x * 32;
    if (FUSED) {
        if (t < 32)
            combine_prelude(base + t, g_e1[1 - p], s_ro_ch, s_ro_k, s_tb,
                            s_a, s_be, s_inv, t);
        __syncthreads();
#pragma unroll 4
        for (int i = 0; i < 32; i++)
            hs[t*HSS + i] = combine_val(s_ro_ch[i], s_ro_k[i], s_tb[i],
                                        s_a[i], s_be[i], s_inv[i], t);
    } else {
#pragma unroll
        for (int i = 0; i < 32; i++) hs[t*HSS + i] = g_h[(size_t)(base + i)*DD + t];
    }
    __syncthreads();
    unsigned long long acc[16];
#pragma unroll
    for (int q = 0; q < 16; q++) acc[q] = 0ull;
    gemm32(W, hs, t, DD, acc);
    float vals[32];
#pragma unroll
    for (int q = 0; q < 16; q++) upk2(acc[q], vals[2*q], vals[2*q+1]);
#pragma unroll
    for (int i = 0; i < 32; i++) g_Wh[(size_t)(base + i)*DD + t] = vals[i];
    float a1t = a1[t], a2t = a2[t];
    int lane = t & 31, w2i = t >> 5;
#pragma unroll
    for (int i = 0; i < 32; i++) {
        float s1 = vals[i] * a1t, s2 = vals[i] * a2t;
#pragma unroll
        for (int off = 16; off; off >>= 1) {
            s1 += __shfl_xor_sync(0xffffffffu, s1, off);
            s2 += __shfl_xor_sync(0xffffffffu, s2, off);
        }
        if (lane == 0) { red[0][w2i][i] = s1; red[1][w2i][i] = s2; }
    }
    __syncthreads();
    if (t < 64) {
        int which = t >> 5, i = t & 31;
        float s = red[which][0][i] + red[which][1][i] + red[which][2][i] + red[which][3][i];
        if (which == 0) g_e1[p][base + i] = s; else g_e2[base + i] = s;
    }
}

// ---------------- csort: warp-sorted 128-elem chunks of packed keys ----------------
__device__ __forceinline__ void ce64(unsigned long long& a, unsigned long long& b,
                                     bool up) {
    if (up ? (a > b) : (a < b)) { unsigned long long t = a; a = b; b = t; }
}

__global__ void __launch_bounds__(512) csort_kernel() {
    int b = blockIdx.x;
    int w = threadIdx.x >> 5, lane = threadIdx.x & 31;
    unsigned long long v[4];
#pragma unroll
    for (int q = 0; q < 4; q++) {
        int e = lane + 32*q;
        int idx = w*125 + e;
        v[q] = (e < 125)
             ? (((unsigned long long)xf(g_e2[b*NN + idx]) << 11) | (unsigned int)idx)
             : 0xFFFFFFFFFFFFFFFFull;
    }
#pragma unroll
    for (int k = 2; k <= 128; k <<= 1) {
#pragma unroll
        for (int j = 64; j >= 32; j >>= 1) {
            if (j <= (k >> 1)) {
                int qb = j >> 5;
#pragma unroll
                for (int qa = 0; qa < 4; qa++) {
                    if ((qa & qb) == 0) {
                        bool up = (((lane + 32*qa) & k) == 0);
                        ce64(v[qa], v[qa | qb], up);
                    }
                }
            }
        }
        int j0 = ((k >> 1) < 16) ? (k >> 1) : 16;
        for (int j = j0; j >= 1; j >>= 1) {
#pragma unroll
            for (int q = 0; q < 4; q++) {
                unsigned long long pv = __shfl_xor_sync(0xffffffffu, v[q], j);
                bool up = (((lane + 32*q) & k) == 0);
                bool lower = ((lane & j) == 0);
                bool asc = (lower == up);
                if (asc ? (pv < v[q]) : (pv > v[q])) v[q] = pv;
            }
        }
    }
#pragma unroll
    for (int q = 0; q < 4; q++)
        g_ck[b*2048 + w*128 + lane + 32*q] = v[q];
}

// ---------------- rank2: thread per (node, chunk); 16-lane segmented reduce ----------------
__global__ void __launch_bounds__(256) rank2_kernel(int p) {
    __shared__ unsigned long long sk[16*CKS];
    int blk = blockIdx.x;
    int b = blk / 125, sub = blk % 125;
    int tid = threadIdx.x;            // 256 = 16 nodes x 16 chunks
    // load 16 chunks with padded stride CKS
    for (int i = tid; i < 2048; i += 256) {
        int c = i >> 7, e = i & 127;
        sk[c*CKS + e] = g_ck[b*2048 + i];
    }
    __syncthreads();
    unsigned int um = 0;
#pragma unroll
    for (int c = 0; c < 16; c++) {
        unsigned int ux = (unsigned int)(sk[c*CKS + 124] >> 11);
        um = um > ux ? um : ux;
    }
    float e2m = ixf(um);
    if (sub == 0 && tid == 0) g_e2max[b] = e2m;
    int nl = tid >> 4, ch = tid & 15;
    int j = sub*16 + nl;
    float e2j = g_e2[b*NN + j];
    unsigned long long keyj = ((unsigned long long)xf(e2j) << 11) | (unsigned int)j;
    unsigned long long keyk = ((unsigned long long)xf(-g_e1[p][b*NN + j]) << 11);
    int cb = ch*CKS;
    int lo1 = 0, lo2 = 0;
#pragma unroll
    for (int half = 64; half >= 1; half >>= 1) {
        if (sk[cb + lo1 + half - 1] < keyj) lo1 += half;
        if (sk[cb + lo2 + half - 1] < keyk) lo2 += half;
    }
    lo1 += (sk[cb + lo1] < keyj);
    lo2 += (sk[cb + lo2] < keyk);
#pragma unroll
    for (int off = 8; off >= 1; off >>= 1) {
        lo1 += __shfl_xor_sync(0xffffffffu, lo1, off);
        lo2 += __shfl_xor_sync(0xffffffffu, lo2, off);
    }
    if (ch == 0) {
        g_perm[b*NPAD + lo1] = j;
        float ev = e2j - e2m;
        g_u1[b*NN + lo1] = __expf(ev);
        g_u2[b*NN + lo1] = __expf(0.2f * ev);
        g_k[b*NN + j] = lo2;
    }
}

// ---------------- scanAB: gather once; emit local prefix tables + chunk totals ----------------
__global__ void scanAB_kernel() {
    __shared__ float su1[CH], su2[CH];
    __shared__ int sperm[CH];
    int b = blockIdx.x / NCH, c = blockIdx.x % NCH;
    int d = threadIdx.x;
    int k0 = c * CH;
    if (d < CH) {
        su1[d] = g_u1[b*NN + k0 + d];
        su2[d] = g_u2[b*NN + k0 + d];
        sperm[d] = g_perm[b*NPAD + k0 + d];
    }
    __syncthreads();
    float w[CH];
#pragma unroll
    for (int k = 0; k < CH; k++) w[k] = g_Wh[((size_t)b*NN + sperm[k])*DD + d];
    size_t rowbase = ((size_t)b*NP1 + k0)*DD + d;
    float f = 0.f, bk = 0.f;
#pragma unroll
    for (int k = 0; k < CH; k++) {
        g_P2l[rowbase + (size_t)k*DD] = f;
        g_P1l[rowbase + (size_t)k*DD] = bk;
        f  = fmaf(su2[k], w[k], f);
        bk = fmaf(su1[k], w[k], bk);
    }
    if (c == NCH - 1) {
        g_P2l[rowbase + (size_t)CH*DD] = f;
        g_P1l[rowbase + (size_t)CH*DD] = bk;
    }
    g_chF[(b*NCH + c)*DD + d] = f;
    g_chB[(b*NCH + c)*DD + d] = bk;
    if (d == 0) {
        float s = 0.f;
#pragma unroll
        for (int k = 0; k < CH; k++) { g_P2ls[b*NP1 + k0 + k] = s; s += su2[k]; }
        if (c == NCH - 1) g_P2ls[b*NP1 + NN] = s;
        g_chFs[b*NCH + c] = s;
    }
    if (d == 1) {
        float s = 0.f;
#pragma unroll
        for (int k = 0; k < CH; k++) { g_P1ls[b*NP1 + k0 + k] = s; s += su1[k]; }
        if (c == NCH - 1) g_P1ls[b*NP1 + NN] = s;
        g_chBs[b*NCH + c] = s;
    }
}

// ---------------- scanC: F and B chains in separate blocks (grid = 2*BB) ----------------
__global__ void scanC_kernel() {
    int b = blockIdx.x >> 1;
    bool isF = (blockIdx.x & 1) == 0;
    int d = threadIdx.x;
    const float* src = isF ? g_chF : g_chB;
    float* dst = isF ? g_chF2 : g_chB2;
    float s = 0.f;
    float v[GT];
    for (int tile = 0; tile < 5; tile++) {
        int c0 = tile*GT;
#pragma unroll
        for (int r = 0; r < GT; r++) v[r] = src[(b*NCH + c0 + r)*DD + d];
#pragma unroll
        for (int r = 0; r < GT; r++) { float x = v[r]; v[r] = s; s += x; }
#pragma unroll
        for (int r = 0; r < GT; r++) dst[(b*NCH + c0 + r)*DD + d] = v[r];
    }
    if (!isF) g_TB[b*DD + d] = s;
    if (d == 0) {
        const float* ssrc = isF ? g_chFs : g_chBs;
        float* sdst = isF ? g_chFs2 : g_chBs2;
        float sc = 0.f;
#pragma unroll 5
        for (int c = 0; c < NCH; c++) {
            float x = ssrc[b*NCH + c];
            sdst[b*NCH + c] = sc;
            sc += x;
        }
        if (!isF) g_TBs[b] = sc;
    }
}

// ---------------- proj (fused combine) ----------------
__global__ void proj_kernel(const float* __restrict__ pw, const float* __restrict__ pb,
                            float* __restrict__ out, int p) {
    __shared__ float hs[DD*HSS];
    __shared__ int s_ro_ch[32], s_ro_k[32], s_tb[32];
    __shared__ float s_a[32], s_be[32], s_inv[32];
    int t = threadIdx.x;              // 64
    int base = blockIdx.x * 32;
    if (t < 32)
        combine_prelude(base + t, g_e1[p], s_ro_ch, s_ro_k, s_tb, s_a, s_be, s_inv, t);
    __syncthreads();
#pragma unroll 2
    for (int i = 0; i < 32; i++) {
        hs[t*HSS + i]        = combine_val(s_ro_ch[i], s_ro_k[i], s_tb[i],
                                           s_a[i], s_be[i], s_inv[i], t);
        hs[(t + 64)*HSS + i] = combine_val(s_ro_ch[i], s_ro_k[i], s_tb[i],
                                           s_a[i], s_be[i], s_inv[i], t + 64);
    }
    __syncthreads();
    unsigned long long acc[16];
    float bv = pb[t];
    unsigned long long b2 = pk2(bv, bv);
#pragma unroll
    for (int q = 0; q < 16; q++) acc[q] = b2;
    gemm32(pw, hs, t, OO, acc);
#pragma unroll
    for (int q = 0; q < 16; q++) {
        float lo, hi; upk2(acc[q], lo, hi);
        int i = 2*q;
        out[(size_t)(base + i)*OO + t] = lo;
        out[(size_t)(base + i + 1)*OO + t] = hi;
    }
}

extern "C" void kernel_launch(void* const* d_in, const int* in_sizes, int n_in,
                              void* d_out, int out_size) {
    const float* coords = (const float*)d_in[0];
    const float* enc_w0 = (const float*)d_in[1];
    const float* enc_b0 = (const float*)d_in[2];
    const float* enc_w1 = (const float*)d_in[3];
    const float* enc_b1 = (const float*)d_in[4];
    const float* gat_W  = (const float*)d_in[5];
    const float* gat_a1 = (const float*)d_in[6];
    const float* gat_a2 = (const float*)d_in[7];
    const float* proj_w = (const float*)d_in[8];
    const float* proj_b = (const float*)d_in[9];
    float* out = (float*)d_out;

    enc_kernel<<<BN/32, 128>>>(coords, enc_w0, enc_b0, enc_w1, enc_b1);
    for (int l = 0; l < NL; l++) {
        int p = l & 1;
        if (l == 0)
            whe_kernel<false><<<BN/32, 128>>>(gat_W, gat_a1, gat_a2, p);
        else
            whe_kernel<true><<<BN/32, 128>>>(gat_W + (size_t)l*DD*DD,
                                             gat_a1 + l*DD, gat_a2 + l*DD, p);
        csort_kernel<<<BB, 512>>>();
        rank2_kernel<<<BB*125, 256>>>(p);
        scanAB_kernel<<<BB*NCH, 128>>>();
        scanC_kernel<<<2*BB, 128>>>();
    }
    proj_kernel<<<BN/32, 64>>>(proj_w, proj_b, out, (NL - 1) & 1);
}